// round 2
// baseline (speedup 1.0000x reference)
#include <cuda_runtime.h>

#define D_MODEL 512
#define NHEADS  8
#define DH      64
#define BATCH   8
#define SEQ     512
// M for projections = BATCH*SEQ = 4096

// ---------------- scratch (device globals; no allocations allowed) ----------
__device__ float g_Q[BATCH * NHEADS * SEQ * DH];   // [b][h][t][d]
__device__ float g_K[BATCH * NHEADS * SEQ * DH];
__device__ float g_V[BATCH * NHEADS * SEQ * DH];
__device__ float g_S[BATCH * NHEADS * SEQ * SEQ];  // [b][h][t][s] scores (64MB)
__device__ float g_C[BATCH * SEQ * D_MODEL];       // context [b][t][h*64+d]

// ---------------------------------------------------------------------------
// NT GEMM: C[m,n] = sum_k A[m,k] * B[n,k] (+bias[n]), both K-contiguous.
// 64x64 block tile, 16-deep k tile, 4x4 per thread (256 threads).
// CMODE 0: C stored row-major [M,512] (ld=512).
// CMODE 1: C scattered to QKV layout [b][h][t][d] (M=4096, N=512 assumed).
// ---------------------------------------------------------------------------
template <int CMODE>
__global__ void __launch_bounds__(256) gemm_nt(
    const float* __restrict__ A, int lda, int sA,
    const float* __restrict__ Bm, int ldb, int sB,
    float* __restrict__ C, int sC,
    const float* __restrict__ bias,
    int K)
{
    const int batch = blockIdx.z;
    A  += (size_t)batch * sA;
    Bm += (size_t)batch * sB;
    C  += (size_t)batch * sC;

    __shared__ float As[16][68];
    __shared__ float Bs[16][68];

    const int tx = threadIdx.x;          // 0..15
    const int ty = threadIdx.y;          // 0..15
    const int tid = ty * 16 + tx;
    const int m0 = blockIdx.x * 64;
    const int n0 = blockIdx.y * 64;

    const int lrow = tid >> 2;           // 0..63
    const int lk4  = (tid & 3) << 2;     // 0,4,8,12

    float acc[4][4] = {};

    for (int k0 = 0; k0 < K; k0 += 16) {
        float4 a = *(const float4*)&A [(size_t)(m0 + lrow) * lda + k0 + lk4];
        float4 b = *(const float4*)&Bm[(size_t)(n0 + lrow) * ldb + k0 + lk4];
        As[lk4 + 0][lrow] = a.x; As[lk4 + 1][lrow] = a.y;
        As[lk4 + 2][lrow] = a.z; As[lk4 + 3][lrow] = a.w;
        Bs[lk4 + 0][lrow] = b.x; Bs[lk4 + 1][lrow] = b.y;
        Bs[lk4 + 2][lrow] = b.z; Bs[lk4 + 3][lrow] = b.w;
        __syncthreads();
        #pragma unroll
        for (int kk = 0; kk < 16; kk++) {
            float4 av = *(const float4*)&As[kk][tx << 2];
            float4 bv = *(const float4*)&Bs[kk][ty << 2];
            float am[4] = {av.x, av.y, av.z, av.w};
            float bn[4] = {bv.x, bv.y, bv.z, bv.w};
            #pragma unroll
            for (int i = 0; i < 4; i++)
                #pragma unroll
                for (int j = 0; j < 4; j++)
                    acc[i][j] += am[i] * bn[j];
        }
        __syncthreads();
    }

    #pragma unroll
    for (int i = 0; i < 4; i++) {
        const int m = m0 + (tx << 2) + i;
        #pragma unroll
        for (int j = 0; j < 4; j++) {
            const int n = n0 + (ty << 2) + j;
            float v = acc[i][j];
            if (bias) v += bias[n];
            if (CMODE == 0) {
                C[(size_t)m * 512 + n] = v;
            } else {
                const int bb = m >> 9, t = m & 511, h = n >> 6, d = n & 63;
                C[(((size_t)(bb * NHEADS + h) * SEQ + t) * DH) + d] = v;
            }
        }
    }
}

// ---------------------------------------------------------------------------
// Position term: S[b,h,t,s] += sum_d Q[b,h,t,d] * rel[t,s,h*64+d]
// One block per (t,h); Q for all 8 batches staged in smem (warp-broadcast
// reads). 128 threads x 4 s-rows each. rel streamed once (512MB total).
// ---------------------------------------------------------------------------
__global__ void __launch_bounds__(128) pos_kernel(
    const float* __restrict__ rel, const float* __restrict__ Q,
    float* __restrict__ S)
{
    const int t = blockIdx.x;
    const int h = blockIdx.y;
    __shared__ float Qs[8][64];

    const int tid = threadIdx.x;
    {
        const int b  = tid >> 4;            // 0..7
        const int d4 = (tid & 15) << 2;     // 0..60
        *(float4*)&Qs[b][d4] =
            *(const float4*)&Q[(((size_t)(b * NHEADS + h) * SEQ + t) * DH) + d4];
    }
    __syncthreads();

    const int s0 = tid << 2;                // 4 s-rows per thread
    const float* relp = rel + ((size_t)t * SEQ + s0) * D_MODEL + h * DH;

    float acc[4][8] = {};
    #pragma unroll
    for (int dq = 0; dq < 16; dq++) {
        float4 r0 = *(const float4*)&relp[0 * D_MODEL + (dq << 2)];
        float4 r1 = *(const float4*)&relp[1 * D_MODEL + (dq << 2)];
        float4 r2 = *(const float4*)&relp[2 * D_MODEL + (dq << 2)];
        float4 r3 = *(const float4*)&relp[3 * D_MODEL + (dq << 2)];
        #pragma unroll
        for (int b = 0; b < 8; b++) {
            float4 q = *(const float4*)&Qs[b][dq << 2];   // broadcast across warp
            acc[0][b] += r0.x * q.x + r0.y * q.y + r0.z * q.z + r0.w * q.w;
            acc[1][b] += r1.x * q.x + r1.y * q.y + r1.z * q.z + r1.w * q.w;
            acc[2][b] += r2.x * q.x + r2.y * q.y + r2.z * q.z + r2.w * q.w;
            acc[3][b] += r3.x * q.x + r3.y * q.y + r3.z * q.z + r3.w * q.w;
        }
    }

    #pragma unroll
    for (int b = 0; b < 8; b++) {
        float* sp = &S[(((size_t)(b * NHEADS + h) * SEQ + t) * SEQ) + s0];
        float4 sv = *(float4*)sp;
        sv.x += acc[0][b]; sv.y += acc[1][b];
        sv.z += acc[2][b]; sv.w += acc[3][b];
        *(float4*)sp = sv;
    }
}

// ---------------------------------------------------------------------------
// Row softmax over s (512 elements), scale 1/sqrt(64)=0.125 fused.
// ---------------------------------------------------------------------------
__global__ void __launch_bounds__(256) softmax_kernel(float* __restrict__ S)
{
    float* p = S + (size_t)blockIdx.x * SEQ;
    const int tid = threadIdx.x;

    float v0 = p[tid]       * 0.125f;
    float v1 = p[tid + 256] * 0.125f;

    __shared__ float redm[8];
    __shared__ float reds[8];

    float m = fmaxf(v0, v1);
    #pragma unroll
    for (int o = 16; o > 0; o >>= 1) m = fmaxf(m, __shfl_xor_sync(~0u, m, o));
    if ((tid & 31) == 0) redm[tid >> 5] = m;
    __syncthreads();
    m = redm[0];
    #pragma unroll
    for (int i = 1; i < 8; i++) m = fmaxf(m, redm[i]);

    float e0 = __expf(v0 - m);
    float e1 = __expf(v1 - m);
    float s = e0 + e1;
    #pragma unroll
    for (int o = 16; o > 0; o >>= 1) s += __shfl_xor_sync(~0u, s, o);
    if ((tid & 31) == 0) reds[tid >> 5] = s;
    __syncthreads();
    s = reds[0];
    #pragma unroll
    for (int i = 1; i < 8; i++) s += reds[i];

    const float inv = __fdividef(1.0f, s);
    p[tid]       = e0 * inv;
    p[tid + 256] = e1 * inv;
}

// ---------------------------------------------------------------------------
// attn @ V (NN GEMM): C_ctx[b, t, h*64+d] = sum_s S[bh][t,s] * V[bh][s,d]
// M=512, N=64, K=512 per (b,h) batch.
// ---------------------------------------------------------------------------
__global__ void __launch_bounds__(256) gemm_av(
    const float* __restrict__ S, const float* __restrict__ V,
    float* __restrict__ C)
{
    const int batch = blockIdx.z;
    const int bb = batch >> 3, h = batch & 7;
    const float* A  = S + (size_t)batch * SEQ * SEQ;
    const float* Bv = V + (size_t)batch * SEQ * DH;

    __shared__ float As[16][68];
    __shared__ float Bs[16][68];

    const int tx = threadIdx.x, ty = threadIdx.y;
    const int tid = ty * 16 + tx;
    const int m0 = blockIdx.x * 64;

    const int lrow = tid >> 2, lk4 = (tid & 3) << 2;   // A tile load
    const int brow = tid >> 4, bn4 = (tid & 15) << 2;  // B tile load

    float acc[4][4] = {};

    for (int k0 = 0; k0 < SEQ; k0 += 16) {
        float4 a = *(const float4*)&A [(size_t)(m0 + lrow) * SEQ + k0 + lk4];
        float4 b = *(const float4*)&Bv[(size_t)(k0 + brow) * DH + bn4];
        As[lk4 + 0][lrow] = a.x; As[lk4 + 1][lrow] = a.y;
        As[lk4 + 2][lrow] = a.z; As[lk4 + 3][lrow] = a.w;
        *(float4*)&Bs[brow][bn4] = b;
        __syncthreads();
        #pragma unroll
        for (int kk = 0; kk < 16; kk++) {
            float4 av = *(const float4*)&As[kk][tx << 2];
            float4 bv = *(const float4*)&Bs[kk][ty << 2];
            float am[4] = {av.x, av.y, av.z, av.w};
            float bn[4] = {bv.x, bv.y, bv.z, bv.w};
            #pragma unroll
            for (int i = 0; i < 4; i++)
                #pragma unroll
                for (int j = 0; j < 4; j++)
                    acc[i][j] += am[i] * bn[j];
        }
        __syncthreads();
    }

    #pragma unroll
    for (int i = 0; i < 4; i++) {
        const int m = m0 + (tx << 2) + i;
        #pragma unroll
        for (int j = 0; j < 4; j++) {
            const int n = (ty << 2) + j;
            C[((size_t)(bb * SEQ + m)) * D_MODEL + h * DH + n] = acc[i][j];
        }
    }
}

// ---------------------------------------------------------------------------
extern "C" void kernel_launch(void* const* d_in, const int* in_sizes, int n_in,
                              void* d_out, int out_size)
{
    const float* x   = (const float*)d_in[0];
    const float* rel = (const float*)d_in[1];
    const float* Wq  = (const float*)d_in[2];
    const float* bq  = (const float*)d_in[3];
    const float* Wk  = (const float*)d_in[4];
    const float* bk  = (const float*)d_in[5];
    const float* Wv  = (const float*)d_in[6];
    const float* bv  = (const float*)d_in[7];
    const float* Wo  = (const float*)d_in[8];
    const float* bo  = (const float*)d_in[9];
    float* out = (float*)d_out;

    float *Q, *Kp, *V, *S, *C;
    cudaGetSymbolAddress((void**)&Q,  g_Q);
    cudaGetSymbolAddress((void**)&Kp, g_K);
    cudaGetSymbolAddress((void**)&V,  g_V);
    cudaGetSymbolAddress((void**)&S,  g_S);
    cudaGetSymbolAddress((void**)&C,  g_C);

    dim3 blk(16, 16);

    // Q/K/V projections: [4096,512] = x[4096,512] @ W[512,512]^T + b
    gemm_nt<1><<<dim3(64, 8, 1), blk>>>(x, 512, 0, Wq, 512, 0, Q,  0, bq, 512);
    gemm_nt<1><<<dim3(64, 8, 1), blk>>>(x, 512, 0, Wk, 512, 0, Kp, 0, bk, 512);
    gemm_nt<1><<<dim3(64, 8, 1), blk>>>(x, 512, 0, Wv, 512, 0, V,  0, bv, 512);

    // content scores: per (b,h): S = Q @ K^T   (M=N=512, K=64, 64 batches)
    gemm_nt<0><<<dim3(8, 8, 64), blk>>>(Q, DH, SEQ * DH,
                                        Kp, DH, SEQ * DH,
                                        S, SEQ * SEQ, nullptr, DH);

    // position scores: S += Q . rel  (streams 512MB of rel once)
    pos_kernel<<<dim3(SEQ, NHEADS), 128>>>(rel, Q, S);

    // softmax rows (scale fused)
    softmax_kernel<<<BATCH * NHEADS * SEQ, 256>>>(S);

    // context = attn @ V, stored as [B, T, D]
    gemm_av<<<dim3(8, 1, 64), blk>>>(S, V, C);

    // output projection: out = C @ Wo^T + bo
    gemm_nt<0><<<dim3(64, 8, 1), blk>>>(C, 512, 0, Wo, 512, 0, out, 0, bo, 512);
}

// round 5
// speedup vs baseline: 1.7510x; 1.7510x over previous
#include <cuda_runtime.h>

#define D_MODEL 512
#define NHEADS  8
#define DH      64
#define BATCH   8
#define SEQ     512

// ---------------- scratch (device globals; no allocations allowed) ----------
__device__ float g_Q[BATCH * NHEADS * SEQ * DH];   // [b][h][t][d]
__device__ float g_K[BATCH * NHEADS * SEQ * DH];
__device__ float g_V[BATCH * NHEADS * SEQ * DH];
__device__ float g_S[BATCH * NHEADS * SEQ * SEQ];  // [b][h][t][s] scores (64MB)
__device__ float g_C[BATCH * SEQ * D_MODEL];       // context [b][t][h*64+d]

// ---------------------------------------------------------------------------
__device__ __forceinline__ unsigned f2tf(float f) {
    unsigned u;
    asm("cvt.rna.tf32.f32 %0, %1;" : "=r"(u) : "f"(f));
    return u;
}

__device__ __forceinline__ void mma8(float* c, const unsigned* a, const unsigned* b) {
    asm volatile(
        "mma.sync.aligned.m16n8k8.row.col.f32.tf32.tf32.f32 "
        "{%0,%1,%2,%3}, {%4,%5,%6,%7}, {%8,%9}, {%0,%1,%2,%3};\n"
        : "+f"(c[0]), "+f"(c[1]), "+f"(c[2]), "+f"(c[3])
        : "r"(a[0]), "r"(a[1]), "r"(a[2]), "r"(a[3]), "r"(b[0]), "r"(b[1]));
}

// ---------------------------------------------------------------------------
// NT GEMM on tensor cores: C[m,n] = sum_k A[m,k]*B[n,k] (+bias), both K-major.
// Block tile 128x128, k-tile 32, 8 warps (64x32 warp tile), tf32 mma.
// CMODE 0: C row-major ld=512.  CMODE 1: scatter to QKV [b][h][t][d].
// ---------------------------------------------------------------------------
template <int CMODE>
__global__ void __launch_bounds__(256) tgemm_nt(
    const float* __restrict__ A, int lda, size_t sA,
    const float* __restrict__ B, int ldb, size_t sB,
    float* __restrict__ C, size_t sC,
    const float* __restrict__ bias, int K)
{
    const int z = blockIdx.z;
    A += (size_t)z * sA;
    B += (size_t)z * sB;
    C += (size_t)z * sC;

    __shared__ unsigned As[128][36];
    __shared__ unsigned Bs[128][36];

    const int tid = threadIdx.x, lane = tid & 31, warp = tid >> 5;
    const int m0 = blockIdx.x * 128, n0 = blockIdx.y * 128;
    const int wm = (warp >> 2) * 64, wn = (warp & 3) * 32;
    const int g = lane >> 2, q = lane & 3;

    float acc[4][4][4] = {};

    for (int k0 = 0; k0 < K; k0 += 32) {
        #pragma unroll
        for (int i = 0; i < 4; i++) {
            int idx = tid + i * 256;            // 0..1023
            int r = idx >> 3, kk = (idx & 7) << 2;
            float4 a = *(const float4*)&A[(size_t)(m0 + r) * lda + k0 + kk];
            float4 b = *(const float4*)&B[(size_t)(n0 + r) * ldb + k0 + kk];
            As[r][kk + 0] = f2tf(a.x); As[r][kk + 1] = f2tf(a.y);
            As[r][kk + 2] = f2tf(a.z); As[r][kk + 3] = f2tf(a.w);
            Bs[r][kk + 0] = f2tf(b.x); Bs[r][kk + 1] = f2tf(b.y);
            Bs[r][kk + 2] = f2tf(b.z); Bs[r][kk + 3] = f2tf(b.w);
        }
        __syncthreads();

        #pragma unroll
        for (int ks = 0; ks < 4; ks++) {
            const int kb = ks * 8;
            unsigned af[4][4], bf[4][2];
            #pragma unroll
            for (int i = 0; i < 4; i++) {
                int r = wm + i * 16 + g;
                af[i][0] = As[r][kb + q];
                af[i][1] = As[r + 8][kb + q];
                af[i][2] = As[r][kb + q + 4];
                af[i][3] = As[r + 8][kb + q + 4];
            }
            #pragma unroll
            for (int j = 0; j < 4; j++) {
                int n = wn + j * 8 + g;
                bf[j][0] = Bs[n][kb + q];
                bf[j][1] = Bs[n][kb + q + 4];
            }
            #pragma unroll
            for (int i = 0; i < 4; i++)
                #pragma unroll
                for (int j = 0; j < 4; j++)
                    mma8(acc[i][j], af[i], bf[j]);
        }
        __syncthreads();
    }

    #pragma unroll
    for (int i = 0; i < 4; i++) {
        #pragma unroll
        for (int j = 0; j < 4; j++) {
            int r0 = m0 + wm + i * 16 + g;
            int c0 = n0 + wn + j * 8 + q * 2;
            float2 v0 = make_float2(acc[i][j][0], acc[i][j][1]);
            float2 v1 = make_float2(acc[i][j][2], acc[i][j][3]);
            if (bias) {
                float2 bb = *(const float2*)&bias[c0];
                v0.x += bb.x; v0.y += bb.y;
                v1.x += bb.x; v1.y += bb.y;
            }
            if (CMODE == 0) {
                *(float2*)&C[(size_t)r0 * 512 + c0] = v0;
                *(float2*)&C[(size_t)(r0 + 8) * 512 + c0] = v1;
            } else {
                int b = r0 >> 9, t = r0 & 511, h = c0 >> 6, d = c0 & 63;
                *(float2*)&C[(((size_t)(b * NHEADS + h) * SEQ + t) * DH) + d] = v0;
                int r1 = r0 + 8;
                b = r1 >> 9; t = r1 & 511;
                *(float2*)&C[(((size_t)(b * NHEADS + h) * SEQ + t) * DH) + d] = v1;
            }
        }
    }
}

// ---------------------------------------------------------------------------
// Position term on tensor cores: S[b,h,t,s] += sum_d Q[b,h,t,d]*rel[t,s,h*64+d]
// One block per (t,h): M=16 (8 real batch rows + 8 zero rows), N=512, K=64.
// A (Q band) lives in registers; rel streamed once through smem (512MB total).
// ---------------------------------------------------------------------------
__global__ void __launch_bounds__(256) pos_tc(
    const float* __restrict__ rel, const float* __restrict__ Q,
    float* __restrict__ S)
{
    const int t = blockIdx.x;
    const int h = blockIdx.y;
    const int tid = threadIdx.x, lane = tid & 31, warp = tid >> 5;
    const int g = lane >> 2, q = lane & 3;

    __shared__ unsigned Rs[64][68];

    // Preload A fragments: row = batch g (0..7 real, +8 rows zero)
    unsigned af[8][4];
    {
        const float* qp = &Q[(((size_t)(g * NHEADS + h) * SEQ + t) * DH)];
        #pragma unroll
        for (int kk = 0; kk < 8; kk++) {
            af[kk][0] = f2tf(qp[kk * 8 + q]);
            af[kk][1] = 0u;
            af[kk][2] = f2tf(qp[kk * 8 + q + 4]);
            af[kk][3] = 0u;
        }
    }

    for (int st = 0; st < 8; st++) {
        const int s_base = st * 64;
        // stage rel tile [64 s][64 d]
        #pragma unroll
        for (int i = 0; i < 4; i++) {
            int idx = tid + i * 256;             // 0..1023 float4s
            int s = idx >> 4, d4 = (idx & 15) << 2;
            float4 r = *(const float4*)&rel[((size_t)t * SEQ + s_base + s) * D_MODEL + h * DH + d4];
            unsigned* dst = &Rs[s][d4];
            dst[0] = f2tf(r.x); dst[1] = f2tf(r.y);
            dst[2] = f2tf(r.z); dst[3] = f2tf(r.w);
        }
        __syncthreads();

        // warp handles n-frag = 8 s-columns at s_base + warp*8
        float acc[4] = {0.f, 0.f, 0.f, 0.f};
        const int n0 = warp * 8;
        #pragma unroll
        for (int kk = 0; kk < 8; kk++) {
            unsigned bf[2];
            bf[0] = Rs[n0 + g][kk * 8 + q];
            bf[1] = Rs[n0 + g][kk * 8 + q + 4];
            mma8(acc, af[kk], bf);
        }

        // RMW into S: rows = batch g (real), cols = s_base + n0 + q*2
        {
            const int s = s_base + n0 + q * 2;
            float* sp = &S[(((size_t)(g * NHEADS + h) * SEQ + t) * SEQ) + s];
            float2 v = *(float2*)sp;
            v.x += acc[0]; v.y += acc[1];
            *(float2*)sp = v;
        }
        __syncthreads();
    }
}

// ---------------------------------------------------------------------------
// Row softmax over s (512 elements), scale 1/sqrt(64)=0.125 fused.
// ---------------------------------------------------------------------------
__global__ void __launch_bounds__(256) softmax_kernel(float* __restrict__ S)
{
    float* p = S + (size_t)blockIdx.x * SEQ;
    const int tid = threadIdx.x;

    float v0 = p[tid]       * 0.125f;
    float v1 = p[tid + 256] * 0.125f;

    __shared__ float redm[8];
    __shared__ float reds[8];

    float m = fmaxf(v0, v1);
    #pragma unroll
    for (int o = 16; o > 0; o >>= 1) m = fmaxf(m, __shfl_xor_sync(~0u, m, o));
    if ((tid & 31) == 0) redm[tid >> 5] = m;
    __syncthreads();
    m = redm[0];
    #pragma unroll
    for (int i = 1; i < 8; i++) m = fmaxf(m, redm[i]);

    float e0 = __expf(v0 - m);
    float e1 = __expf(v1 - m);
    float s = e0 + e1;
    #pragma unroll
    for (int o = 16; o > 0; o >>= 1) s += __shfl_xor_sync(~0u, s, o);
    if ((tid & 31) == 0) reds[tid >> 5] = s;
    __syncthreads();
    s = reds[0];
    #pragma unroll
    for (int i = 1; i < 8; i++) s += reds[i];

    const float inv = __fdividef(1.0f, s);
    p[tid]       = e0 * inv;
    p[tid + 256] = e1 * inv;
}

// ---------------------------------------------------------------------------
// attn @ V on tensor cores (NN): per (b,h): C[t,d] = sum_s S[t,s]*V[s,d]
// M=512, N=64, K=512. Block 128x64, 8 warps (32x32 warp tile).
// ---------------------------------------------------------------------------
__global__ void __launch_bounds__(256) tgemm_av(
    const float* __restrict__ S, const float* __restrict__ V,
    float* __restrict__ C)
{
    const int z = blockIdx.z;         // b*8 + h
    const int b = z >> 3, h = z & 7;
    const float* A  = S + (size_t)z * SEQ * SEQ;
    const float* Bv = V + (size_t)z * SEQ * DH;

    __shared__ unsigned As[128][36];
    __shared__ unsigned Bs[64][36];

    const int tid = threadIdx.x, lane = tid & 31, warp = tid >> 5;
    const int m0 = blockIdx.x * 128;
    const int wm = (warp >> 1) * 32, wn = (warp & 1) * 32;
    const int g = lane >> 2, q = lane & 3;

    float acc[2][4][4] = {};

    for (int k0 = 0; k0 < SEQ; k0 += 32) {
        #pragma unroll
        for (int i = 0; i < 4; i++) {
            int idx = tid + i * 256;
            int r = idx >> 3, kk = (idx & 7) << 2;
            float4 a = *(const float4*)&A[(size_t)(m0 + r) * SEQ + k0 + kk];
            As[r][kk + 0] = f2tf(a.x); As[r][kk + 1] = f2tf(a.y);
            As[r][kk + 2] = f2tf(a.z); As[r][kk + 3] = f2tf(a.w);
        }
        #pragma unroll
        for (int i = 0; i < 2; i++) {
            int idx = tid + i * 256;             // 512 float4s: [32 s][64 d]
            int s = idx >> 4, d4 = (idx & 15) << 2;
            float4 v = *(const float4*)&Bv[(size_t)(k0 + s) * DH + d4];
            Bs[d4 + 0][s] = f2tf(v.x); Bs[d4 + 1][s] = f2tf(v.y);
            Bs[d4 + 2][s] = f2tf(v.z); Bs[d4 + 3][s] = f2tf(v.w);
        }
        __syncthreads();

        #pragma unroll
        for (int ks = 0; ks < 4; ks++) {
            const int kb = ks * 8;
            unsigned af[2][4], bf[4][2];
            #pragma unroll
            for (int i = 0; i < 2; i++) {
                int r = wm + i * 16 + g;
                af[i][0] = As[r][kb + q];
                af[i][1] = As[r + 8][kb + q];
                af[i][2] = As[r][kb + q + 4];
                af[i][3] = As[r + 8][kb + q + 4];
            }
            #pragma unroll
            for (int j = 0; j < 4; j++) {
                int n = wn + j * 8 + g;
                bf[j][0] = Bs[n][kb + q];
                bf[j][1] = Bs[n][kb + q + 4];
            }
            #pragma unroll
            for (int i = 0; i < 2; i++)
                #pragma unroll
                for (int j = 0; j < 4; j++)
                    mma8(acc[i][j], af[i], bf[j]);
        }
        __syncthreads();
    }

    #pragma unroll
    for (int i = 0; i < 2; i++) {
        #pragma unroll
        for (int j = 0; j < 4; j++) {
            int r0 = m0 + wm + i * 16 + g;
            int d  = wn + j * 8 + q * 2;
            *(float2*)&C[((size_t)(b * SEQ) + r0) * D_MODEL + h * DH + d] =
                make_float2(acc[i][j][0], acc[i][j][1]);
            *(float2*)&C[((size_t)(b * SEQ) + r0 + 8) * D_MODEL + h * DH + d] =
                make_float2(acc[i][j][2], acc[i][j][3]);
        }
    }
}

// ---------------------------------------------------------------------------
extern "C" void kernel_launch(void* const* d_in, const int* in_sizes, int n_in,
                              void* d_out, int out_size)
{
    const float* x   = (const float*)d_in[0];
    const float* rel = (const float*)d_in[1];
    const float* Wq  = (const float*)d_in[2];
    const float* bq  = (const float*)d_in[3];
    const float* Wk  = (const float*)d_in[4];
    const float* bk  = (const float*)d_in[5];
    const float* Wv  = (const float*)d_in[6];
    const float* bv  = (const float*)d_in[7];
    const float* Wo  = (const float*)d_in[8];
    const float* bo  = (const float*)d_in[9];
    float* out = (float*)d_out;

    float *Q, *Kp, *V, *S, *C;
    cudaGetSymbolAddress((void**)&Q,  g_Q);
    cudaGetSymbolAddress((void**)&Kp, g_K);
    cudaGetSymbolAddress((void**)&V,  g_V);
    cudaGetSymbolAddress((void**)&S,  g_S);
    cudaGetSymbolAddress((void**)&C,  g_C);

    // Q/K/V projections: [4096,512] = x @ W^T + b, scattered to [b][h][t][d]
    tgemm_nt<1><<<dim3(32, 4, 1), 256>>>(x, 512, 0, Wq, 512, 0, Q,  0, bq, 512);
    tgemm_nt<1><<<dim3(32, 4, 1), 256>>>(x, 512, 0, Wk, 512, 0, Kp, 0, bk, 512);
    tgemm_nt<1><<<dim3(32, 4, 1), 256>>>(x, 512, 0, Wv, 512, 0, V,  0, bv, 512);

    // content scores per (b,h): S = Q @ K^T  (M=N=512, K=64, 64 batches)
    tgemm_nt<0><<<dim3(4, 4, 64), 256>>>(Q, DH, (size_t)SEQ * DH,
                                         Kp, DH, (size_t)SEQ * DH,
                                         S, (size_t)SEQ * SEQ, nullptr, DH);

    // position scores: S += Q . rel  (streams 512MB of rel once)
    pos_tc<<<dim3(SEQ, NHEADS), 256>>>(rel, Q, S);

    // softmax rows (scale fused)
    softmax_kernel<<<BATCH * NHEADS * SEQ, 256>>>(S);

    // context = attn @ V -> [B, T, D]
    tgemm_av<<<dim3(4, 1, 64), 256>>>(S, V, C);

    // output projection: out = C @ Wo^T + bo
    tgemm_nt<0><<<dim3(32, 4, 1), 256>>>(C, 512, 0, Wo, 512, 0, out, 0, bo, 512);
}

// round 7
// speedup vs baseline: 2.1778x; 1.2437x over previous
#include <cuda_runtime.h>

#define D_MODEL 512
#define NHEADS  8
#define DH      64
#define BATCH   8
#define SEQ     512

// ---------------- scratch (device globals; no allocations allowed) ----------
__device__ float g_Q[BATCH * NHEADS * SEQ * DH];   // [b][h][t][d]
__device__ float g_K[BATCH * NHEADS * SEQ * DH];
__device__ float g_V[BATCH * NHEADS * SEQ * DH];
__device__ float g_S[BATCH * NHEADS * SEQ * SEQ];  // scores then probs (64MB)
__device__ float g_C[BATCH * SEQ * D_MODEL];       // context [b][t][h*64+d]

// ---------------------------------------------------------------------------
__device__ __forceinline__ unsigned f2tf(float f) {
    unsigned u;
    asm("cvt.rna.tf32.f32 %0, %1;" : "=r"(u) : "f"(f));
    return u;
}

__device__ __forceinline__ void mma8(float* c, const unsigned* a, const unsigned* b) {
    asm volatile(
        "mma.sync.aligned.m16n8k8.row.col.f32.tf32.tf32.f32 "
        "{%0,%1,%2,%3}, {%4,%5,%6,%7}, {%8,%9}, {%0,%1,%2,%3};\n"
        : "+f"(c[0]), "+f"(c[1]), "+f"(c[2]), "+f"(c[3])
        : "r"(a[0]), "r"(a[1]), "r"(a[2]), "r"(a[3]), "r"(b[0]), "r"(b[1]));
}

__device__ __forceinline__ void cp16(void* smem_dst, const void* gsrc) {
    unsigned s = (unsigned)__cvta_generic_to_shared(smem_dst);
    asm volatile("cp.async.cg.shared.global [%0], [%1], 16;\n" :: "r"(s), "l"(gsrc));
}
__device__ __forceinline__ void cp_commit() {
    asm volatile("cp.async.commit_group;\n" ::: "memory");
}

// ---------------------------------------------------------------------------
// Shared tensor-core NT GEMM core: C[m,n] = sum_k A[m,k]*B[n,k] (+bias).
// Block tile 128x128, k-tile 32, 8 warps (64x32 warp tile), tf32 mma.
// CMODE 0: C row-major ld=512.  CMODE 1: scatter to QKV [b][h][t][d].
// ---------------------------------------------------------------------------
template <int CMODE>
__device__ __forceinline__ void gemm_core(
    const float* __restrict__ A, int lda,
    const float* __restrict__ B, int ldb,
    float* __restrict__ C,
    const float* __restrict__ bias, int K,
    unsigned As[128][36], unsigned Bs[128][36])
{
    const int tid = threadIdx.x, lane = tid & 31, warp = tid >> 5;
    const int m0 = blockIdx.x * 128, n0 = blockIdx.y * 128;
    const int wm = (warp >> 2) * 64, wn = (warp & 3) * 32;
    const int g = lane >> 2, q = lane & 3;

    float acc[4][4][4] = {};

    for (int k0 = 0; k0 < K; k0 += 32) {
        #pragma unroll
        for (int i = 0; i < 4; i++) {
            int idx = tid + i * 256;
            int r = idx >> 3, kk = (idx & 7) << 2;
            float4 a = *(const float4*)&A[(size_t)(m0 + r) * lda + k0 + kk];
            float4 b = *(const float4*)&B[(size_t)(n0 + r) * ldb + k0 + kk];
            As[r][kk + 0] = f2tf(a.x); As[r][kk + 1] = f2tf(a.y);
            As[r][kk + 2] = f2tf(a.z); As[r][kk + 3] = f2tf(a.w);
            Bs[r][kk + 0] = f2tf(b.x); Bs[r][kk + 1] = f2tf(b.y);
            Bs[r][kk + 2] = f2tf(b.z); Bs[r][kk + 3] = f2tf(b.w);
        }
        __syncthreads();

        #pragma unroll
        for (int ks = 0; ks < 4; ks++) {
            const int kb = ks * 8;
            unsigned af[4][4], bf[4][2];
            #pragma unroll
            for (int i = 0; i < 4; i++) {
                int r = wm + i * 16 + g;
                af[i][0] = As[r][kb + q];
                af[i][1] = As[r + 8][kb + q];
                af[i][2] = As[r][kb + q + 4];
                af[i][3] = As[r + 8][kb + q + 4];
            }
            #pragma unroll
            for (int j = 0; j < 4; j++) {
                int n = wn + j * 8 + g;
                bf[j][0] = Bs[n][kb + q];
                bf[j][1] = Bs[n][kb + q + 4];
            }
            #pragma unroll
            for (int i = 0; i < 4; i++)
                #pragma unroll
                for (int j = 0; j < 4; j++)
                    mma8(acc[i][j], af[i], bf[j]);
        }
        __syncthreads();
    }

    #pragma unroll
    for (int i = 0; i < 4; i++) {
        #pragma unroll
        for (int j = 0; j < 4; j++) {
            int r0 = m0 + wm + i * 16 + g;
            int c0 = n0 + wn + j * 8 + q * 2;
            float2 v0 = make_float2(acc[i][j][0], acc[i][j][1]);
            float2 v1 = make_float2(acc[i][j][2], acc[i][j][3]);
            if (bias) {
                float2 bb = *(const float2*)&bias[c0];
                v0.x += bb.x; v0.y += bb.y;
                v1.x += bb.x; v1.y += bb.y;
            }
            if (CMODE == 0) {
                *(float2*)&C[(size_t)r0 * 512 + c0] = v0;
                *(float2*)&C[(size_t)(r0 + 8) * 512 + c0] = v1;
            } else {
                int b = r0 >> 9, t = r0 & 511, h = c0 >> 6, d = c0 & 63;
                *(float2*)&C[(((size_t)(b * NHEADS + h) * SEQ + t) * DH) + d] = v0;
                int r1 = r0 + 8;
                b = r1 >> 9; t = r1 & 511;
                *(float2*)&C[(((size_t)(b * NHEADS + h) * SEQ + t) * DH) + d] = v1;
            }
        }
    }
}

// ---- wrapper kernels ------------------------------------------------------
__global__ void __launch_bounds__(256) qkv_gemm(
    const float* __restrict__ x,
    const float* __restrict__ Wq, const float* __restrict__ bq, float* Qo,
    const float* __restrict__ Wk, const float* __restrict__ bk, float* Ko,
    const float* __restrict__ Wv, const float* __restrict__ bv, float* Vo)
{
    __shared__ unsigned As[128][36];
    __shared__ unsigned Bs[128][36];
    const float* W; const float* b; float* o;
    if (blockIdx.z == 0)      { W = Wq; b = bq; o = Qo; }
    else if (blockIdx.z == 1) { W = Wk; b = bk; o = Ko; }
    else                      { W = Wv; b = bv; o = Vo; }
    gemm_core<1>(x, 512, W, 512, o, b, 512, As, Bs);
}

__global__ void __launch_bounds__(256) content_gemm(
    const float* __restrict__ Q, const float* __restrict__ K,
    float* __restrict__ S)
{
    __shared__ unsigned As[128][36];
    __shared__ unsigned Bs[128][36];
    const size_t z = blockIdx.z;
    gemm_core<0>(Q + z * SEQ * DH, DH, K + z * SEQ * DH, DH,
                 S + z * SEQ * SEQ, nullptr, DH, As, Bs);
}

__global__ void __launch_bounds__(256) out_gemm(
    const float* __restrict__ C, const float* __restrict__ Wo,
    const float* __restrict__ bo, float* __restrict__ out)
{
    __shared__ unsigned As[128][36];
    __shared__ unsigned Bs[128][36];
    gemm_core<0>(C, 512, Wo, 512, out, bo, 512, As, Bs);
}

// ---------------------------------------------------------------------------
// Fused position + softmax. One block per (t,h).
// acc init = content scores (read from S); rel streamed via cp.async
// double-buffered 64-s tiles; row softmax in registers; probs written to S.
// ---------------------------------------------------------------------------
__device__ __forceinline__ void load_rel_tile(
    float (*dst)[68], const float* __restrict__ src, int tid)
{
    #pragma unroll
    for (int i = 0; i < 4; i++) {
        int idx = tid + i * 256;
        int s = idx >> 4, d4 = (idx & 15) << 2;
        cp16(&dst[s][d4], src + (size_t)s * D_MODEL + d4);
    }
    cp_commit();
}

__device__ __forceinline__ void comp_tile(
    float* acc4, const float (*Rs)[68], const unsigned af[8][2],
    int warp, int g, int q)
{
    const int n0 = warp * 8;
    #pragma unroll
    for (int kk = 0; kk < 8; kk++) {
        unsigned b[2];
        b[0] = f2tf(Rs[n0 + g][kk * 8 + q]);
        b[1] = f2tf(Rs[n0 + g][kk * 8 + q + 4]);
        unsigned a[4] = {af[kk][0], 0u, af[kk][1], 0u};
        mma8(acc4, a, b);
    }
}

__global__ void __launch_bounds__(256) pos_softmax(
    const float* __restrict__ rel, const float* __restrict__ Q,
    float* __restrict__ S)
{
    const int t = blockIdx.x, h = blockIdx.y;
    const int tid = threadIdx.x, lane = tid & 31, warp = tid >> 5;
    const int g = lane >> 2, q = lane & 3;

    __shared__ float Rs[2][64][68];        // double-buffered rel tiles (raw fp32)
    __shared__ float red[2][8][8];         // [max|sum][warp][batch]

    // A fragments from Q (rows 0-7 = batches, rows 8-15 zero)
    unsigned af[8][2];
    {
        const float* qp = &Q[(((size_t)(g * NHEADS + h) * SEQ + t) * DH)];
        #pragma unroll
        for (int kk = 0; kk < 8; kk++) {
            af[kk][0] = f2tf(qp[kk * 8 + q]);
            af[kk][1] = f2tf(qp[kk * 8 + q + 4]);
        }
    }

    // init accumulators with content scores
    float acc[8][4];
    const size_t srow = ((size_t)(g * NHEADS + h) * SEQ + t) * SEQ;
    #pragma unroll
    for (int ti = 0; ti < 8; ti++) {
        float2 c = *(const float2*)&S[srow + ti * 64 + warp * 8 + q * 2];
        acc[ti][0] = c.x; acc[ti][1] = c.y; acc[ti][2] = 0.f; acc[ti][3] = 0.f;
    }

    const float* rbase = rel + (size_t)t * SEQ * D_MODEL + h * DH;

    load_rel_tile(Rs[0], rbase, tid);
    load_rel_tile(Rs[1], rbase + (size_t)64 * D_MODEL, tid);

    #pragma unroll
    for (int ti = 0; ti < 8; ti++) {
        if (ti < 7) asm volatile("cp.async.wait_group 1;\n" ::: "memory");
        else        asm volatile("cp.async.wait_group 0;\n" ::: "memory");
        __syncthreads();
        comp_tile(acc[ti], Rs[ti & 1], af, warp, g, q);
        __syncthreads();
        if (ti < 6)
            load_rel_tile(Rs[ti & 1], rbase + (size_t)(ti + 2) * 64 * D_MODEL, tid);
    }

    // ---- row softmax (row = batch g; 512 s spread over warps/q/tiles) ----
    float m = -1e30f;
    #pragma unroll
    for (int ti = 0; ti < 8; ti++) m = fmaxf(m, fmaxf(acc[ti][0], acc[ti][1]));
    m = fmaxf(m, __shfl_xor_sync(~0u, m, 1));
    m = fmaxf(m, __shfl_xor_sync(~0u, m, 2));
    if (q == 0) red[0][warp][g] = m;
    __syncthreads();
    float M = red[0][0][g];
    #pragma unroll
    for (int w = 1; w < 8; w++) M = fmaxf(M, red[0][w][g]);

    float sum = 0.f;
    #pragma unroll
    for (int ti = 0; ti < 8; ti++) {
        acc[ti][0] = __expf((acc[ti][0] - M) * 0.125f);
        acc[ti][1] = __expf((acc[ti][1] - M) * 0.125f);
        sum += acc[ti][0] + acc[ti][1];
    }
    sum += __shfl_xor_sync(~0u, sum, 1);
    sum += __shfl_xor_sync(~0u, sum, 2);
    if (q == 0) red[1][warp][g] = sum;
    __syncthreads();
    float tot = 0.f;
    #pragma unroll
    for (int w = 0; w < 8; w++) tot += red[1][w][g];
    const float inv = __fdividef(1.0f, tot);

    #pragma unroll
    for (int ti = 0; ti < 8; ti++)
        *(float2*)&S[srow + ti * 64 + warp * 8 + q * 2] =
            make_float2(acc[ti][0] * inv, acc[ti][1] * inv);
}

// ---------------------------------------------------------------------------
// attn @ V on tensor cores (NN): per (b,h): C[t,d] = sum_s S[t,s]*V[s,d]
// ---------------------------------------------------------------------------
__global__ void __launch_bounds__(256) tgemm_av(
    const float* __restrict__ S, const float* __restrict__ V,
    float* __restrict__ C)
{
    const int z = blockIdx.z;
    const int b = z >> 3, h = z & 7;
    const float* A  = S + (size_t)z * SEQ * SEQ;
    const float* Bv = V + (size_t)z * SEQ * DH;

    __shared__ unsigned As[128][36];
    __shared__ unsigned Bs[64][36];

    const int tid = threadIdx.x, lane = tid & 31, warp = tid >> 5;
    const int m0 = blockIdx.x * 128;
    const int wm = (warp >> 1) * 32, wn = (warp & 1) * 32;
    const int g = lane >> 2, q = lane & 3;

    float acc[2][4][4] = {};

    for (int k0 = 0; k0 < SEQ; k0 += 32) {
        #pragma unroll
        for (int i = 0; i < 4; i++) {
            int idx = tid + i * 256;
            int r = idx >> 3, kk = (idx & 7) << 2;
            float4 a = *(const float4*)&A[(size_t)(m0 + r) * SEQ + k0 + kk];
            As[r][kk + 0] = f2tf(a.x); As[r][kk + 1] = f2tf(a.y);
            As[r][kk + 2] = f2tf(a.z); As[r][kk + 3] = f2tf(a.w);
        }
        #pragma unroll
        for (int i = 0; i < 2; i++) {
            int idx = tid + i * 256;
            int s = idx >> 4, d4 = (idx & 15) << 2;
            float4 v = *(const float4*)&Bv[(size_t)(k0 + s) * DH + d4];
            Bs[d4 + 0][s] = f2tf(v.x); Bs[d4 + 1][s] = f2tf(v.y);
            Bs[d4 + 2][s] = f2tf(v.z); Bs[d4 + 3][s] = f2tf(v.w);
        }
        __syncthreads();

        #pragma unroll
        for (int ks = 0; ks < 4; ks++) {
            const int kb = ks * 8;
            unsigned af[2][4], bf[4][2];
            #pragma unroll
            for (int i = 0; i < 2; i++) {
                int r = wm + i * 16 + g;
                af[i][0] = As[r][kb + q];
                af[i][1] = As[r + 8][kb + q];
                af[i][2] = As[r][kb + q + 4];
                af[i][3] = As[r + 8][kb + q + 4];
            }
            #pragma unroll
            for (int j = 0; j < 4; j++) {
                int n = wn + j * 8 + g;
                bf[j][0] = Bs[n][kb + q];
                bf[j][1] = Bs[n][kb + q + 4];
            }
            #pragma unroll
            for (int i = 0; i < 2; i++)
                #pragma unroll
                for (int j = 0; j < 4; j++)
                    mma8(acc[i][j], af[i], bf[j]);
        }
        __syncthreads();
    }

    #pragma unroll
    for (int i = 0; i < 2; i++) {
        #pragma unroll
        for (int j = 0; j < 4; j++) {
            int r0 = m0 + wm + i * 16 + g;
            int d  = wn + j * 8 + q * 2;
            *(float2*)&C[((size_t)(b * SEQ) + r0) * D_MODEL + h * DH + d] =
                make_float2(acc[i][j][0], acc[i][j][1]);
            *(float2*)&C[((size_t)(b * SEQ) + r0 + 8) * D_MODEL + h * DH + d] =
                make_float2(acc[i][j][2], acc[i][j][3]);
        }
    }
}

// ---------------------------------------------------------------------------
extern "C" void kernel_launch(void* const* d_in, const int* in_sizes, int n_in,
                              void* d_out, int out_size)
{
    const float* x   = (const float*)d_in[0];
    const float* rel = (const float*)d_in[1];
    const float* Wq  = (const float*)d_in[2];
    const float* bq  = (const float*)d_in[3];
    const float* Wk  = (const float*)d_in[4];
    const float* bk  = (const float*)d_in[5];
    const float* Wv  = (const float*)d_in[6];
    const float* bv  = (const float*)d_in[7];
    const float* Wo  = (const float*)d_in[8];
    const float* bo  = (const float*)d_in[9];
    float* out = (float*)d_out;

    float *Q, *Kp, *V, *S, *C;
    cudaGetSymbolAddress((void**)&Q,  g_Q);
    cudaGetSymbolAddress((void**)&Kp, g_K);
    cudaGetSymbolAddress((void**)&V,  g_V);
    cudaGetSymbolAddress((void**)&S,  g_S);
    cudaGetSymbolAddress((void**)&C,  g_C);

    // Q/K/V projections in one launch (z selects W/b/dst)
    qkv_gemm<<<dim3(32, 4, 3), 256>>>(x, Wq, bq, Q, Wk, bk, Kp, Wv, bv, V);

    // content scores per (b,h): S = Q @ K^T  (M=N=512, K=64, 64 batches)
    content_gemm<<<dim3(4, 4, 64), 256>>>(Q, Kp, S);

    // fused: S = softmax((S + Q.rel)/8)  — streams rel once
    pos_softmax<<<dim3(SEQ, NHEADS), 256>>>(rel, Q, S);

    // context = attn @ V -> [B, T, D]
    tgemm_av<<<dim3(4, 1, 64), 256>>>(S, V, C);

    // output projection: out = C @ Wo^T + bo
    out_gemm<<<dim3(32, 4, 1), 256>>>(C, Wo, bo, out);
}